// round 1
// baseline (speedup 1.0000x reference)
#include <cuda_runtime.h>
#include <math.h>

#define NT 2000
#define NPT 255
#define NC 16
#define NM 32
#define NG 16

#define SB_STRIDE 520                 // padded row stride (floats) for softmaxed B in smem
#define BETA_FLOATS (192*256)         // 192 node slots x (16 states x 16 gens)
#define SMEM_FLOATS (BETA_FLOATS + NC*SB_STRIDE)
#define SMEM_BYTES  (SMEM_FLOATS * 4)

__device__ float g_smA[NC*NC*NG];
__device__ float g_smB[NC*NM*NG];
__device__ float g_smPi[NC*NG];

// ---------------------------------------------------------------------------
// Prologue: compute the three softmaxes once. 1 block, 256 threads.
// A: softmax over p (axis 0) for each (c,g). B: softmax over m (axis 1) for
// each (c,g). Pi: softmax over c (axis 0) for each g.
// ---------------------------------------------------------------------------
__global__ void htmm_softmax_kernel(const float* __restrict__ A,
                                    const float* __restrict__ B,
                                    const float* __restrict__ Pi) {
    int tid = threadIdx.x;            // 256 threads
    int c = tid >> 4;
    int g = tid & 15;

    // A column (over p) for (c,g)
    {
        float mx = -1e30f;
        #pragma unroll
        for (int p = 0; p < NC; p++)
            mx = fmaxf(mx, A[p*NC*NG + c*NG + g]);
        float e[NC]; float s = 0.f;
        #pragma unroll
        for (int p = 0; p < NC; p++) {
            e[p] = expf(A[p*NC*NG + c*NG + g] - mx);
            s += e[p];
        }
        float rs = 1.f / s;
        #pragma unroll
        for (int p = 0; p < NC; p++)
            g_smA[p*NC*NG + c*NG + g] = e[p] * rs;
    }
    // B row (over m) for (c,g)
    {
        float mx = -1e30f;
        #pragma unroll
        for (int m = 0; m < NM; m++)
            mx = fmaxf(mx, B[c*NM*NG + m*NG + g]);
        float s = 0.f;
        #pragma unroll
        for (int m = 0; m < NM; m++)
            s += expf(B[c*NM*NG + m*NG + g] - mx);
        float rs = 1.f / s;
        #pragma unroll
        for (int m = 0; m < NM; m++)
            g_smB[c*NM*NG + m*NG + g] = expf(B[c*NM*NG + m*NG + g] - mx) * rs;
    }
    // Pi (over c) for g
    if (tid < NG) {
        int gg = tid;
        float mx = -1e30f;
        #pragma unroll
        for (int cc = 0; cc < NC; cc++)
            mx = fmaxf(mx, Pi[cc*NG + gg]);
        float s = 0.f;
        #pragma unroll
        for (int cc = 0; cc < NC; cc++)
            s += expf(Pi[cc*NG + gg] - mx);
        float rs = 1.f / s;
        #pragma unroll
        for (int cc = 0; cc < NC; cc++)
            g_smPi[cc*NG + gg] = expf(Pi[cc*NG + gg] - mx) * rs;
    }
}

// ---------------------------------------------------------------------------
// Main kernel: one CTA per tree, level-synchronous upward pass in smem.
// Thread layout: pblk = tid&3 (covers states p = pblk+4*i), g = (tid>>2)&15,
// ng = tid>>6 (node group; 64 threads / 2 warps per node).
// beta slot layout: [slot][c][g], slot stride 256 floats.
// Level l+1 (children) lives in one ping-pong region, level l written to the
// other: region(l) = ((7-l)&1) ? slots[128..192) : slots[0..128).
// ---------------------------------------------------------------------------
__global__ void __launch_bounds__(256, 1)
htmm_upward_kernel(const int* __restrict__ x, float* __restrict__ out) {
    extern __shared__ float sm[];
    float* sBeta = sm;                      // 192*256 floats
    float* sB    = sm + BETA_FLOATS;        // 16*520 floats (padded rows)
    __shared__ int   sx[NPT];
    __shared__ float sacc[256];

    const int tid  = threadIdx.x;
    const int tree = blockIdx.x;
    const int pblk = tid & 3;
    const int g    = (tid >> 2) & 15;
    const int ng   = tid >> 6;

    // Stage: A -> sBeta scratch (dead space before leaves), B -> padded smem, x -> smem
    for (int i = tid; i < NC*NC*NG; i += 256) sBeta[i] = g_smA[i];
    for (int i = tid; i < NC*NM*NG; i += 256) {
        int c = i >> 9;                     // / (NM*NG) = /512
        int r = i & 511;
        sB[c*SB_STRIDE + r] = g_smB[i];
    }
    for (int i = tid; i < NPT; i += 256) sx[i] = x[tree*NPT + i];
    __syncthreads();

    // A rows for this thread's (pblk, g): p = pblk + 4*ip, all 16 c. 64 regs.
    float Areg[4][NC];
    #pragma unroll
    for (int ip = 0; ip < 4; ip++) {
        int p = pblk + 4*ip;
        #pragma unroll
        for (int c = 0; c < NC; c++)
            Areg[ip][c] = sBeta[p*NC*NG + c*NG + g];
    }
    __syncthreads();   // everyone read A before leaves overwrite the scratch

    float accll = 0.f;

    // ---- Leaves (level 7): 128 nodes, region slots [0..128) ----
    for (int j = ng; j < 128; j += 4) {
        const int xo = sx[127 + j]*NG + g;
        float v[4]; float s = 0.f;
        #pragma unroll
        for (int i = 0; i < 4; i++) {
            int c = pblk + 4*i;
            float pi = g_smPi[c*NG + g];          // tiny, L2-resident
            float b  = sB[c*SB_STRIDE + xo];      // conflict-free (stride 520)
            v[i] = pi * b;
            s += v[i];
        }
        s += __shfl_xor_sync(0xffffffffu, s, 1);
        s += __shfl_xor_sync(0xffffffffu, s, 2);
        float rs = __fdividef(1.f, s);
        #pragma unroll
        for (int i = 0; i < 4; i++) {
            int c = pblk + 4*i;
            sBeta[j*256 + c*NG + g] = v[i] * rs;
        }
        accll += 0.25f * __logf(s);
    }
    __syncthreads();

    // ---- Internal levels l = 6..0 ----
    #pragma unroll 1
    for (int l = 6; l >= 0; l--) {
        const int P     = 1 << l;
        const int cbase = ((6 - l) & 1) ? 128 : 0;   // region of level l+1
        const int pbase = ((7 - l) & 1) ? 128 : 0;   // region of level l
        const int lstart = P - 1;
        for (int j = ng; j < P; j += 4) {
            const float* b0 = &sBeta[(cbase + 2*j)*256 + g];
            const float* b1 = b0 + 256;
            float bsum[NC];
            #pragma unroll
            for (int c = 0; c < NC; c++)
                bsum[c] = b0[c*NG] + b1[c*NG];       // warp-broadcast, conflict-free

            float t[4];
            #pragma unroll
            for (int ip = 0; ip < 4; ip++) {
                float a = 0.f;
                #pragma unroll
                for (int c = 0; c < NC; c++)
                    a = fmaf(Areg[ip][c], bsum[c], a);
                t[ip] = a;
            }

            const int xo = sx[lstart + j]*NG + g;
            float bv[4]; float s = 0.f;
            #pragma unroll
            for (int ip = 0; ip < 4; ip++) {
                int p = pblk + 4*ip;
                float e = sB[p*SB_STRIDE + xo];
                bv[ip] = e * t[ip];
                s += bv[ip];
            }
            s += __shfl_xor_sync(0xffffffffu, s, 1);
            s += __shfl_xor_sync(0xffffffffu, s, 2);
            // nu = 0.5*s (BF=2 mean). The 0.5 cancels in the normalization and
            // contributes -ln2 per internal node to ll (added at the end).
            float rs = __fdividef(1.f, s);
            #pragma unroll
            for (int ip = 0; ip < 4; ip++) {
                int p = pblk + 4*ip;
                sBeta[(pbase + j)*256 + p*NG + g] = bv[ip] * rs;
            }
            accll += 0.25f * __logf(s);
        }
        __syncthreads();
    }

    // ---- Deterministic per-g reduction of ll over the 16 threads sharing g ----
    sacc[tid] = accll;
    __syncthreads();
    if (tid < NG) {
        const int gg = tid;
        float s = 0.f;
        #pragma unroll
        for (int k = 0; k < 16; k++) {
            int srct = (k >> 2)*64 + gg*4 + (k & 3);   // ng = k>>2, pblk = k&3
            s += sacc[srct];
        }
        // 127 internal nodes each owe a -ln2 from the folded BF mean
        out[tree*NG + gg] = s - 127.0f * 0.69314718055994530942f;
    }
}

// ---------------------------------------------------------------------------
extern "C" void kernel_launch(void* const* d_in, const int* in_sizes, int n_in,
                              void* d_out, int out_size) {
    const float* A  = (const float*)d_in[0];
    const float* B  = (const float*)d_in[1];
    const float* Pi = (const float*)d_in[2];
    const int*   x  = (const int*)  d_in[3];
    // d_in[4..8]: edge_parents/children, leaves, trees_ind, batch — structure is
    // regular (child(n) = 2n+1, 2n+2 within each 255-node tree), so unused.
    float* out = (float*)d_out;

    cudaFuncSetAttribute(htmm_upward_kernel,
                         cudaFuncAttributeMaxDynamicSharedMemorySize, SMEM_BYTES);

    htmm_softmax_kernel<<<1, 256>>>(A, B, Pi);
    htmm_upward_kernel<<<NT, 256, SMEM_BYTES>>>(x, out);
}

// round 2
// speedup vs baseline: 1.6751x; 1.6751x over previous
#include <cuda_runtime.h>
#include <cuda_fp16.h>
#include <math.h>

#define NT 2000
#define NPT 255
#define NC 16
#define NM 32
#define NG 16

#define SB_STRIDE 520                       // padded row stride (floats) for softmaxed B
#define BETA_SLOTS 96                       // ping-pong: 64 (levels 6,4,2,0) + 32 (levels 5,3,1)
#define BETA_HALFS (BETA_SLOTS*256)         // [slot][g][c], c contiguous, half
#define DYN_SMEM_BYTES (BETA_HALFS*2 + NC*SB_STRIDE*4)   // 49152 + 33280 = 82432

__device__ float g_smA[NC*NC*NG];
__device__ float g_smB[NC*NM*NG];
__device__ float g_smPi[NC*NG];

// ---------------------------------------------------------------------------
// packed f32x2 helpers (FFMA2 only reachable via PTX)
// ---------------------------------------------------------------------------
__device__ __forceinline__ unsigned long long pack2(float lo, float hi) {
    unsigned long long r;
    asm("mov.b64 %0, {%1, %2};" : "=l"(r) : "f"(lo), "f"(hi));
    return r;
}
__device__ __forceinline__ void ffma2(unsigned long long& d,
                                      unsigned long long a, unsigned long long b) {
    asm("fma.rn.f32x2 %0, %1, %2, %0;" : "+l"(d) : "l"(a), "l"(b));
}
__device__ __forceinline__ float unpack_sum(unsigned long long v) {
    float lo, hi;
    asm("mov.b64 {%0, %1}, %2;" : "=f"(lo), "=f"(hi) : "l"(v));
    return lo + hi;
}

// ---------------------------------------------------------------------------
// Prologue: the three softmaxes, once. 1 block, 256 threads.
// ---------------------------------------------------------------------------
__global__ void htmm_softmax_kernel(const float* __restrict__ A,
                                    const float* __restrict__ B,
                                    const float* __restrict__ Pi) {
    int tid = threadIdx.x;
    int c = tid >> 4;
    int g = tid & 15;
    {   // A: softmax over p for each (c,g)
        float mx = -1e30f;
        #pragma unroll
        for (int p = 0; p < NC; p++) mx = fmaxf(mx, A[p*NC*NG + c*NG + g]);
        float e[NC]; float s = 0.f;
        #pragma unroll
        for (int p = 0; p < NC; p++) { e[p] = expf(A[p*NC*NG + c*NG + g] - mx); s += e[p]; }
        float rs = 1.f / s;
        #pragma unroll
        for (int p = 0; p < NC; p++) g_smA[p*NC*NG + c*NG + g] = e[p] * rs;
    }
    {   // B: softmax over m for each (c,g)
        float mx = -1e30f;
        #pragma unroll
        for (int m = 0; m < NM; m++) mx = fmaxf(mx, B[c*NM*NG + m*NG + g]);
        float s = 0.f;
        #pragma unroll
        for (int m = 0; m < NM; m++) s += expf(B[c*NM*NG + m*NG + g] - mx);
        float rs = 1.f / s;
        #pragma unroll
        for (int m = 0; m < NM; m++)
            g_smB[c*NM*NG + m*NG + g] = expf(B[c*NM*NG + m*NG + g] - mx) * rs;
    }
    if (tid < NG) {   // Pi: softmax over c for each g
        int gg = tid;
        float mx = -1e30f;
        #pragma unroll
        for (int cc = 0; cc < NC; cc++) mx = fmaxf(mx, Pi[cc*NG + gg]);
        float s = 0.f;
        #pragma unroll
        for (int cc = 0; cc < NC; cc++) s += expf(Pi[cc*NG + gg] - mx);
        float rs = 1.f / s;
        #pragma unroll
        for (int cc = 0; cc < NC; cc++)
            g_smPi[cc*NG + gg] = expf(Pi[cc*NG + gg] - mx) * rs;
    }
}

// ---------------------------------------------------------------------------
// Main kernel: one CTA per tree, 2 CTAs/SM.
// Thread layout: pblk = tid&3 (states p = pblk+4*ip), g = (tid>>2)&15, ng = tid>>6.
// beta: half, layout [slot][g][c] (c contiguous -> half2 loads).
// Level 7 (leaves) fused into level 6: leaf betas live only in registers.
// base(l) = ((6-l)&1) ? 64 : 0.
// ---------------------------------------------------------------------------
__global__ void __launch_bounds__(256, 2)
htmm_upward_kernel(const int* __restrict__ x, float* __restrict__ out) {
    extern __shared__ __align__(16) unsigned char smraw[];
    __half* sBetaH = (__half*)smraw;                       // 96*256 halfs
    float*  sB     = (float*)(smraw + BETA_HALFS*2);       // 16*520 floats
    __shared__ int   sx[NPT];
    __shared__ float sacc[256];

    const int tid  = threadIdx.x;
    const int tree = blockIdx.x;
    const int pblk = tid & 3;
    const int g    = (tid >> 2) & 15;
    const int ng   = tid >> 6;

    // ---- Stage: A -> fp32 scratch overlaid on beta region, B -> padded smem, x ----
    float* Ascratch = (float*)smraw;                       // 16KB < 48KB region
    for (int i = tid; i < NC*NC*NG; i += 256) Ascratch[i] = g_smA[i];
    for (int i = tid; i < NC*NM*NG; i += 256) {
        int c = i >> 9;
        sB[c*SB_STRIDE + (i & 511)] = g_smB[i];
    }
    for (int i = tid; i < NPT; i += 256) sx[i] = x[tree*NPT + i];
    __syncthreads();

    // A rows packed along c pairs: A2[ip][c2] = {A[p][2c2][g], A[p][2c2+1][g]}, p = pblk+4*ip
    unsigned long long A2[4][8];
    #pragma unroll
    for (int ip = 0; ip < 4; ip++) {
        int p = pblk + 4*ip;
        #pragma unroll
        for (int c2 = 0; c2 < 8; c2++)
            A2[ip][c2] = pack2(Ascratch[p*NC*NG + (2*c2)*NG + g],
                               Ascratch[p*NC*NG + (2*c2+1)*NG + g]);
    }
    // Pi in registers (kills per-iteration LDG from round 1)
    float Pi_r[NC];
    #pragma unroll
    for (int c = 0; c < NC; c++) Pi_r[c] = g_smPi[c*NG + g];
    __syncthreads();   // A scratch may now be overwritten by level-6 beta writes

    float accll = 0.f;

    // ---- Level 6 with fused leaves: 64 nodes, write slots [0..64) ----
    for (int j = ng; j < 64; j += 4) {
        const int xo0 = sx[127 + 2*j    ]*NG + g;
        const int xo1 = sx[127 + 2*j + 1]*NG + g;
        float s0 = 0.f, s1 = 0.f;
        unsigned long long t0a[4] = {0ull,0ull,0ull,0ull};
        unsigned long long t1a[4] = {0ull,0ull,0ull,0ull};
        #pragma unroll
        for (int c2 = 0; c2 < 8; c2++) {
            const int c0 = 2*c2, c1 = 2*c2 + 1;
            float a0 = Pi_r[c0] * sB[c0*SB_STRIDE + xo0];
            float a1 = Pi_r[c1] * sB[c1*SB_STRIDE + xo0];
            s0 += a0 + a1;
            unsigned long long v0 = pack2(a0, a1);
            float b0 = Pi_r[c0] * sB[c0*SB_STRIDE + xo1];
            float b1 = Pi_r[c1] * sB[c1*SB_STRIDE + xo1];
            s1 += b0 + b1;
            unsigned long long v1 = pack2(b0, b1);
            #pragma unroll
            for (int ip = 0; ip < 4; ip++) { ffma2(t0a[ip], A2[ip][c2], v0);
                                             ffma2(t1a[ip], A2[ip][c2], v1); }
        }
        float rs0 = __fdividef(1.f, s0);
        float rs1 = __fdividef(1.f, s1);
        accll += 0.25f * (__logf(s0) + __logf(s1));   // leaf ll, x4-shared per g

        const int xo = sx[63 + j]*NG + g;
        float s = 0.f; float bv[4];
        #pragma unroll
        for (int ip = 0; ip < 4; ip++) {
            float t = unpack_sum(t0a[ip])*rs0 + unpack_sum(t1a[ip])*rs1;
            float e = sB[(pblk + 4*ip)*SB_STRIDE + xo];
            bv[ip] = e * t;
            s += bv[ip];
        }
        s += __shfl_xor_sync(0xffffffffu, s, 1);
        s += __shfl_xor_sync(0xffffffffu, s, 2);
        float rs = __fdividef(1.f, s);
        #pragma unroll
        for (int ip = 0; ip < 4; ip++)
            sBetaH[j*256 + g*NC + pblk + 4*ip] = __float2half_rn(bv[ip] * rs);
        accll += 0.25f * __logf(s);
    }
    __syncthreads();

    // ---- Levels 5..0 ----
    #pragma unroll 1
    for (int l = 5; l >= 0; l--) {
        const int P      = 1 << l;
        const int cbase  = ((5 - l) & 1) ? 64 : 0;   // children (level l+1)
        const int pbase  = ((6 - l) & 1) ? 64 : 0;   // this level
        const int lstart = P - 1;
        for (int j = ng; j < P; j += 4) {
            const __half2* h0 = (const __half2*)(sBetaH + (cbase + 2*j    )*256 + g*NC);
            const __half2* h1 = (const __half2*)(sBetaH + (cbase + 2*j + 1)*256 + g*NC);
            unsigned long long acc[4] = {0ull,0ull,0ull,0ull};
            #pragma unroll
            for (int c2 = 0; c2 < 8; c2++) {
                __half2 hs = __hadd2(h0[c2], h1[c2]);        // beta_ch0 + beta_ch1
                float2  f  = __half22float2(hs);
                unsigned long long b2 = pack2(f.x, f.y);
                #pragma unroll
                for (int ip = 0; ip < 4; ip++) ffma2(acc[ip], A2[ip][c2], b2);
            }
            const int xo = sx[lstart + j]*NG + g;
            float s = 0.f; float bv[4];
            #pragma unroll
            for (int ip = 0; ip < 4; ip++) {
                float t = unpack_sum(acc[ip]);
                float e = sB[(pblk + 4*ip)*SB_STRIDE + xo];
                bv[ip] = e * t;
                s += bv[ip];
            }
            s += __shfl_xor_sync(0xffffffffu, s, 1);
            s += __shfl_xor_sync(0xffffffffu, s, 2);
            // nu = 0.5*s (BF=2 mean); 0.5 cancels in normalization, -ln2 folded at end
            float rs = __fdividef(1.f, s);
            #pragma unroll
            for (int ip = 0; ip < 4; ip++)
                sBetaH[(pbase + j)*256 + g*NC + pblk + 4*ip] = __float2half_rn(bv[ip] * rs);
            accll += 0.25f * __logf(s);
        }
        __syncthreads();
    }

    // ---- Deterministic per-g reduction over the 16 threads sharing g ----
    sacc[tid] = accll;
    __syncthreads();
    if (tid < NG) {
        const int gg = tid;
        float s = 0.f;
        #pragma unroll
        for (int k = 0; k < 16; k++) {
            int srct = (k >> 2)*64 + gg*4 + (k & 3);
            s += sacc[srct];
        }
        out[tree*NG + gg] = s - 127.0f * 0.69314718055994530942f;  // folded BF=2 means
    }
}

// ---------------------------------------------------------------------------
extern "C" void kernel_launch(void* const* d_in, const int* in_sizes, int n_in,
                              void* d_out, int out_size) {
    const float* A  = (const float*)d_in[0];
    const float* B  = (const float*)d_in[1];
    const float* Pi = (const float*)d_in[2];
    const int*   x  = (const int*)  d_in[3];
    float* out = (float*)d_out;

    cudaFuncSetAttribute(htmm_upward_kernel,
                         cudaFuncAttributeMaxDynamicSharedMemorySize, DYN_SMEM_BYTES);

    htmm_softmax_kernel<<<1, 256>>>(A, B, Pi);
    htmm_upward_kernel<<<NT, 256, DYN_SMEM_BYTES>>>(x, out);
}